// round 2
// baseline (speedup 1.0000x reference)
#include <cuda_runtime.h>
#include <cuda_bf16.h>
#include <cstdint>

// ---------------------------------------------------------------------------
// Problem constants:  x:(2048,64,512) fp32,  Wq/Wk/Wv/Wo:(512,512) fp32
// out = SDPA(x@WqT, x@WkT, x@WvT) @ WoT       H=16, dk=32, S=64
// M = 2048*64 = 131072 rows, D = 512.
// ---------------------------------------------------------------------------

#define D_MODEL   512
#define M_ROWS    131072
#define NUM_HEADS 16
#define SEQ       64
#define DK        32

// Scratch (device globals are the sanctioned scratch mechanism).
__device__ float g_q[(size_t)M_ROWS * D_MODEL];
__device__ float g_k[(size_t)M_ROWS * D_MODEL];
__device__ float g_v[(size_t)M_ROWS * D_MODEL];
__device__ float g_att[(size_t)M_ROWS * D_MODEL];

// Round-to-nearest tf32 (keeps fp32 bit layout, mantissa truncated+rounded).
__device__ __forceinline__ unsigned f2tf32(float f) {
    unsigned r;
    asm("cvt.rna.tf32.f32 %0, %1;" : "=r"(r) : "f"(f));
    return r;
}

// K-permutation within groups of 8 so the (c, c+4) pair a tf32 fragment needs
// sits adjacent in SMEM -> every fragment load is a single LDS.64.
__device__ __forceinline__ int pk8(int k) {
    return (k & ~7) + ((k & 3) << 1) + ((k & 7) >> 2);
}

#define MMA_TF32(d, a0, a1, a2, a3, b0, b1)                                    \
    asm volatile(                                                              \
        "mma.sync.aligned.m16n8k8.row.col.f32.tf32.tf32.f32 "                  \
        "{%0,%1,%2,%3}, {%4,%5,%6,%7}, {%8,%9}, {%0,%1,%2,%3};"                \
        : "+f"(d[0]), "+f"(d[1]), "+f"(d[2]), "+f"(d[3])                       \
        : "r"(a0), "r"(a1), "r"(a2), "r"(a3), "r"(b0), "r"(b1))

// ---------------------------------------------------------------------------
// GEMM: C[M,512] = A[M,512] @ W[512,512]^T   (torch Linear, bias-free)
// Block tile 128x128, BK=32, 256 threads = 8 warps (2 along M x 4 along N),
// warp tile 64x32. Register-prefetch pipeline over 16 K-iterations.
// ---------------------------------------------------------------------------
__global__ void __launch_bounds__(256, 1)
gemm512_tf32(const float* __restrict__ A, const float* __restrict__ W,
             float* __restrict__ C) {
    __shared__ unsigned As[128][34];
    __shared__ unsigned Bs[128][34];

    const int tid  = threadIdx.x;
    const int lane = tid & 31;
    const int wid  = tid >> 5;
    const int wm   = wid & 1;     // 0..1  (64 rows each)
    const int wn   = wid >> 1;    // 0..3  (32 cols each)
    const int c    = lane & 3;
    const int r8   = lane >> 2;

    const int m0 = blockIdx.x * 128;
    const int n0 = blockIdx.y * 128;

    // Loader mapping: 2 threads per row, 16 contiguous cols each.
    const int lrow = tid >> 1;
    const int lc0  = (tid & 1) * 16;
    const float* gA = A + (size_t)(m0 + lrow) * D_MODEL + lc0;
    const float* gW = W + (size_t)(n0 + lrow) * D_MODEL + lc0;

    float4 ra[4], rw[4];

    float acc[4][4][4];
#pragma unroll
    for (int mt = 0; mt < 4; mt++)
#pragma unroll
        for (int nt = 0; nt < 4; nt++)
#pragma unroll
            for (int i = 0; i < 4; i++) acc[mt][nt][i] = 0.0f;

    // prologue: load + store tile 0
#pragma unroll
    for (int q = 0; q < 4; q++) {
        ra[q] = *(const float4*)(gA + q * 4);
        rw[q] = *(const float4*)(gW + q * 4);
    }
#pragma unroll
    for (int q = 0; q < 4; q++) {
        const float av[4] = {ra[q].x, ra[q].y, ra[q].z, ra[q].w};
        const float wv[4] = {rw[q].x, rw[q].y, rw[q].z, rw[q].w};
#pragma unroll
        for (int j = 0; j < 4; j++) {
            int pc = pk8(lc0 + q * 4 + j);
            As[lrow][pc] = f2tf32(av[j]);
            Bs[lrow][pc] = f2tf32(wv[j]);
        }
    }

    for (int kt = 0; kt < 16; kt++) {
        __syncthreads();
        if (kt < 15) {
            const int k0 = (kt + 1) * 32;
#pragma unroll
            for (int q = 0; q < 4; q++) {
                ra[q] = *(const float4*)(gA + k0 + q * 4);
                rw[q] = *(const float4*)(gW + k0 + q * 4);
            }
        }

#pragma unroll
        for (int kk = 0; kk < 32; kk += 8) {
            const int kpos = kk + 2 * c;
            unsigned a0[4], a1[4], a2[4], a3[4];
#pragma unroll
            for (int mt = 0; mt < 4; mt++) {
                uint2 lo = *(const uint2*)&As[wm * 64 + mt * 16 + r8][kpos];
                uint2 hi = *(const uint2*)&As[wm * 64 + mt * 16 + 8 + r8][kpos];
                a0[mt] = lo.x; a2[mt] = lo.y; a1[mt] = hi.x; a3[mt] = hi.y;
            }
            unsigned b0[4], b1[4];
#pragma unroll
            for (int nt = 0; nt < 4; nt++) {
                uint2 bb = *(const uint2*)&Bs[wn * 32 + nt * 8 + r8][kpos];
                b0[nt] = bb.x; b1[nt] = bb.y;
            }
#pragma unroll
            for (int mt = 0; mt < 4; mt++)
#pragma unroll
                for (int nt = 0; nt < 4; nt++)
                    MMA_TF32(acc[mt][nt], a0[mt], a1[mt], a2[mt], a3[mt],
                             b0[nt], b1[nt]);
        }

        __syncthreads();
        if (kt < 15) {
#pragma unroll
            for (int q = 0; q < 4; q++) {
                const float av[4] = {ra[q].x, ra[q].y, ra[q].z, ra[q].w};
                const float wv[4] = {rw[q].x, rw[q].y, rw[q].z, rw[q].w};
#pragma unroll
                for (int j = 0; j < 4; j++) {
                    int pc = pk8(lc0 + q * 4 + j);
                    As[lrow][pc] = f2tf32(av[j]);
                    Bs[lrow][pc] = f2tf32(wv[j]);
                }
            }
        }
    }

    // Epilogue: float2 stores (c0,c1 are adjacent columns).
#pragma unroll
    for (int mt = 0; mt < 4; mt++) {
        const int row = m0 + wm * 64 + mt * 16 + r8;
#pragma unroll
        for (int nt = 0; nt < 4; nt++) {
            const int col = n0 + wn * 32 + nt * 8 + 2 * c;
            float2 lo = make_float2(acc[mt][nt][0], acc[mt][nt][1]);
            float2 hi = make_float2(acc[mt][nt][2], acc[mt][nt][3]);
            *(float2*)&C[(size_t)row * D_MODEL + col]       = lo;
            *(float2*)&C[(size_t)(row + 8) * D_MODEL + col] = hi;
        }
    }
}

// ---------------------------------------------------------------------------
// Attention: one block (128 threads, 4 warps) per (batch, head).
// S = (Q K^T) * 1/sqrt(32); softmax rows; O = P V.
// Each warp owns 16 of the 64 query rows.
// ---------------------------------------------------------------------------
__global__ void __launch_bounds__(128, 5)
attn64_tf32(const float* __restrict__ Q, const float* __restrict__ K,
            const float* __restrict__ V, float* __restrict__ O) {
    __shared__ unsigned Qs[64][34];
    __shared__ unsigned Ks[64][34];
    __shared__ unsigned Vt[32][66];      // transposed V, s-dim permuted
    __shared__ unsigned Ps[4][16][66];   // per-warp probabilities, s-permuted

    const int tid  = threadIdx.x;
    const int lane = tid & 31;
    const int w    = tid >> 5;
    const int c    = lane & 3;
    const int r8   = lane >> 2;

    const int bh = blockIdx.x;
    const int b  = bh >> 4;
    const int h  = bh & 15;
    const size_t rbase = (size_t)b * SEQ * D_MODEL + h * DK;

    // Load Q,K (row-major, k-permuted) and V (transposed, s-permuted).
    const int lrow = tid >> 1;          // 0..63
    const int lc0  = (tid & 1) * 16;
    const int prow = pk8(lrow);         // permuted s index for Vt
#pragma unroll
    for (int q = 0; q < 4; q++) {
        float4 vq = *(const float4*)(Q + rbase + (size_t)lrow * D_MODEL + lc0 + q * 4);
        float4 vk = *(const float4*)(K + rbase + (size_t)lrow * D_MODEL + lc0 + q * 4);
        float4 vv = *(const float4*)(V + rbase + (size_t)lrow * D_MODEL + lc0 + q * 4);
        const float aq[4] = {vq.x, vq.y, vq.z, vq.w};
        const float ak[4] = {vk.x, vk.y, vk.z, vk.w};
        const float av[4] = {vv.x, vv.y, vv.z, vv.w};
#pragma unroll
        for (int j = 0; j < 4; j++) {
            int col = lc0 + q * 4 + j;
            int pc  = pk8(col);
            Qs[lrow][pc]   = f2tf32(aq[j]);
            Ks[lrow][pc]   = f2tf32(ak[j]);
            Vt[col][prow]  = f2tf32(av[j]);
        }
    }
    __syncthreads();

    // ---- S = Q K^T ----
    float s[8][4];
#pragma unroll
    for (int nt = 0; nt < 8; nt++)
#pragma unroll
        for (int i = 0; i < 4; i++) s[nt][i] = 0.0f;

#pragma unroll
    for (int kk = 0; kk < 32; kk += 8) {
        const int kpos = kk + 2 * c;
        uint2 alo = *(const uint2*)&Qs[w * 16 + r8][kpos];
        uint2 ahi = *(const uint2*)&Qs[w * 16 + 8 + r8][kpos];
#pragma unroll
        for (int nt = 0; nt < 8; nt++) {
            uint2 bb = *(const uint2*)&Ks[nt * 8 + r8][kpos];
            MMA_TF32(s[nt], alo.x, ahi.x, alo.y, ahi.y, bb.x, bb.y);
        }
    }

    // ---- softmax over 64 columns (4 lanes of the quad hold a full row) ----
    const float scale = 0.17677669529663687f;  // 1/sqrt(32)
#pragma unroll
    for (int nt = 0; nt < 8; nt++)
#pragma unroll
        for (int i = 0; i < 4; i++) s[nt][i] *= scale;

    float m1 = -1e30f, m2 = -1e30f;
#pragma unroll
    for (int nt = 0; nt < 8; nt++) {
        m1 = fmaxf(m1, fmaxf(s[nt][0], s[nt][1]));
        m2 = fmaxf(m2, fmaxf(s[nt][2], s[nt][3]));
    }
    m1 = fmaxf(m1, __shfl_xor_sync(0xffffffffu, m1, 1));
    m1 = fmaxf(m1, __shfl_xor_sync(0xffffffffu, m1, 2));
    m2 = fmaxf(m2, __shfl_xor_sync(0xffffffffu, m2, 1));
    m2 = fmaxf(m2, __shfl_xor_sync(0xffffffffu, m2, 2));

    float sum1 = 0.0f, sum2 = 0.0f;
#pragma unroll
    for (int nt = 0; nt < 8; nt++) {
        s[nt][0] = __expf(s[nt][0] - m1);
        s[nt][1] = __expf(s[nt][1] - m1);
        s[nt][2] = __expf(s[nt][2] - m2);
        s[nt][3] = __expf(s[nt][3] - m2);
        sum1 += s[nt][0] + s[nt][1];
        sum2 += s[nt][2] + s[nt][3];
    }
    sum1 += __shfl_xor_sync(0xffffffffu, sum1, 1);
    sum1 += __shfl_xor_sync(0xffffffffu, sum1, 2);
    sum2 += __shfl_xor_sync(0xffffffffu, sum2, 1);
    sum2 += __shfl_xor_sync(0xffffffffu, sum2, 2);
    const float inv1 = 1.0f / sum1;
    const float inv2 = 1.0f / sum2;

    // Store P into per-warp SMEM in the permuted-A layout.
    const int j0 = 2 * c;
    const int p0 = ((j0 & 3) << 1) + (j0 >> 2);          // pk within group of 8
    const int p1 = (((j0 + 1) & 3) << 1) + ((j0 + 1) >> 2);
#pragma unroll
    for (int nt = 0; nt < 8; nt++) {
        Ps[w][r8][nt * 8 + p0]     = f2tf32(s[nt][0] * inv1);
        Ps[w][r8][nt * 8 + p1]     = f2tf32(s[nt][1] * inv1);
        Ps[w][r8 + 8][nt * 8 + p0] = f2tf32(s[nt][2] * inv2);
        Ps[w][r8 + 8][nt * 8 + p1] = f2tf32(s[nt][3] * inv2);
    }
    __syncwarp();

    // ---- O = P V ----
    float o[4][4];
#pragma unroll
    for (int nt = 0; nt < 4; nt++)
#pragma unroll
        for (int i = 0; i < 4; i++) o[nt][i] = 0.0f;

#pragma unroll
    for (int kk = 0; kk < 64; kk += 8) {
        const int kpos = kk + 2 * c;
        uint2 alo = *(const uint2*)&Ps[w][r8][kpos];
        uint2 ahi = *(const uint2*)&Ps[w][r8 + 8][kpos];
#pragma unroll
        for (int nt = 0; nt < 4; nt++) {
            uint2 bb = *(const uint2*)&Vt[nt * 8 + r8][kpos];
            MMA_TF32(o[nt], alo.x, ahi.x, alo.y, ahi.y, bb.x, bb.y);
        }
    }

    // Store attention output (heads re-interleaved into [M,512]).
    const int row = b * SEQ + w * 16 + r8;
#pragma unroll
    for (int nt = 0; nt < 4; nt++) {
        const int col = h * DK + nt * 8 + 2 * c;
        *(float2*)&O[(size_t)row * D_MODEL + col] =
            make_float2(o[nt][0], o[nt][1]);
        *(float2*)&O[(size_t)(row + 8) * D_MODEL + col] =
            make_float2(o[nt][2], o[nt][3]);
    }
}

// ---------------------------------------------------------------------------
// Launch: 3 projection GEMMs -> attention -> output GEMM (stream-ordered).
// ---------------------------------------------------------------------------
extern "C" void kernel_launch(void* const* d_in, const int* in_sizes, int n_in,
                              void* d_out, int out_size) {
    (void)in_sizes; (void)n_in; (void)out_size;
    const float* x  = (const float*)d_in[0];
    const float* Wq = (const float*)d_in[1];
    const float* Wk = (const float*)d_in[2];
    const float* Wv = (const float*)d_in[3];
    const float* Wo = (const float*)d_in[4];
    float* out = (float*)d_out;

    void *pq, *pk, *pv, *pa;
    cudaGetSymbolAddress(&pq, g_q);
    cudaGetSymbolAddress(&pk, g_k);
    cudaGetSymbolAddress(&pv, g_v);
    cudaGetSymbolAddress(&pa, g_att);

    dim3 grid(M_ROWS / 128, D_MODEL / 128);
    dim3 block(256);

    gemm512_tf32<<<grid, block>>>(x, Wq, (float*)pq);
    gemm512_tf32<<<grid, block>>>(x, Wk, (float*)pk);
    gemm512_tf32<<<grid, block>>>(x, Wv, (float*)pv);

    attn64_tf32<<<M_ROWS / SEQ * NUM_HEADS, 128>>>(
        (const float*)pq, (const float*)pk, (const float*)pv, (float*)pa);

    gemm512_tf32<<<grid, block>>>((const float*)pa, Wo, out);
}

// round 5
// speedup vs baseline: 2.1768x; 2.1768x over previous
#include <cuda_runtime.h>
#include <cuda_bf16.h>
#include <cstdint>

// ---------------------------------------------------------------------------
// x:(2048,64,512) fp32, Wq/Wk/Wv/Wo:(512,512) fp32
// out = SDPA(x@WqT, x@WkT, x@WvT) @ WoT    H=16, dk=32, S=64
// M = 131072 rows, D = 512.
//
// sm_103a-only tcgen05 is NOT available (harness compiles PTX at compute_103),
// so everything runs on mma.sync tf32 — but with:
//   * inputs pre-rounded to tf32 bit patterns and pk8-permuted in gmem
//   * cp.async 3-stage pipelined GEMM (no register staging, no in-kernel cvt)
//   * conflict-free XOR-swizzled SMEM
// R5 fix vs R4: B-fragment base in compute() was missing the wn*32-row
// offset (all N-warps read B rows 0..31) -> rel_err 1.37. Now sB += wn*4096.
// ---------------------------------------------------------------------------

#define D_MODEL   512
#define M_ROWS    131072
#define NUM_HEADS 16
#define SEQ       64
#define DK        32

#define MS        ((size_t)M_ROWS * D_MODEL)
#define WELEMS    ((size_t)D_MODEL * D_MODEL)

// Scratch (device globals are the sanctioned scratch mechanism).
__device__ float g_xt[MS];           // x, tf32-rounded, pk8-permuted cols
__device__ float g_wt[4 * WELEMS];   // Wq,Wk,Wv,Wo, tf32-rounded, permuted
__device__ float g_qkv[3 * MS];      // q, k, v (plain fp32)
__device__ float g_at[MS];           // attn out, tf32-rounded, permuted

// ======================== helpers ==========================================
__device__ __forceinline__ unsigned f2tf32(float f) {
    unsigned r;
    asm("cvt.rna.tf32.f32 %0, %1;" : "=r"(r) : "f"(f));
    return r;
}
__device__ __forceinline__ float rtf(float f) {
    return __uint_as_float(f2tf32(f));
}
__device__ __forceinline__ int pk8(int k) {
    return (k & ~7) + ((k & 3) << 1) + ((k & 7) >> 2);
}
__device__ __forceinline__ uint32_t smem_u32(const void* p) {
    uint32_t a;
    asm("{ .reg .u64 t; cvta.to.shared.u64 t, %1; cvt.u32.u64 %0, t; }"
        : "=r"(a) : "l"(p));
    return a;
}

#define MMA_TF32(d, a0, a1, a2, a3, b0, b1)                                    \
    asm volatile(                                                              \
        "mma.sync.aligned.m16n8k8.row.col.f32.tf32.tf32.f32 "                  \
        "{%0,%1,%2,%3}, {%4,%5,%6,%7}, {%8,%9}, {%0,%1,%2,%3};"                \
        : "+f"(d[0]), "+f"(d[1]), "+f"(d[2]), "+f"(d[3])                       \
        : "r"(a0), "r"(a1), "r"(a2), "r"(a3), "r"(b0), "r"(b1))

#define CPA16(sa, gp)                                                          \
    asm volatile("cp.async.cg.shared.global [%0], [%1], 16;"                   \
                 :: "r"(sa), "l"(gp) : "memory")
#define CPA_COMMIT() asm volatile("cp.async.commit_group;" ::: "memory")
#define CPA_WAIT1()  asm volatile("cp.async.wait_group 1;" ::: "memory")
#define CPA_WAIT0()  asm volatile("cp.async.wait_group 0;" ::: "memory")
#define LDS64(v, a)                                                            \
    asm volatile("ld.shared.v2.u32 {%0,%1}, [%2];"                             \
                 : "=r"((v).x), "=r"((v).y) : "r"(a))

// ======================== prep passes ======================================
// Round to tf32 and permute columns within each group of 8:
// out position p holds logical j where pk8(j)=p:  [j0,j4,j1,j5,j2,j6,j3,j7]
__device__ __forceinline__ void prep_group(const float4* in, float4* out) {
    float4 u = in[0], v = in[1];
    out[0] = make_float4(rtf(u.x), rtf(v.x), rtf(u.y), rtf(v.y));
    out[1] = make_float4(rtf(u.z), rtf(v.z), rtf(u.w), rtf(v.w));
}

__global__ void __launch_bounds__(256)
prep_x_kernel(const float* __restrict__ in, float* __restrict__ out) {
    size_t g = (size_t)blockIdx.x * 256 + threadIdx.x;   // group of 8 floats
    float4 o[2];
    prep_group((const float4*)in + 2 * g, o);
    ((float4*)out)[2 * g]     = o[0];
    ((float4*)out)[2 * g + 1] = o[1];
}

__global__ void __launch_bounds__(256)
prep_w_kernel(const float* __restrict__ w0, const float* __restrict__ w1,
              const float* __restrict__ w2, const float* __restrict__ w3,
              float* __restrict__ out) {
    size_t g = (size_t)blockIdx.x * 256 + threadIdx.x;   // group of 8 floats
    int wsel = (int)(g >> 15);                            // 32768 groups per W
    const float* src = wsel == 0 ? w0 : wsel == 1 ? w1 : wsel == 2 ? w2 : w3;
    size_t off = (g & 32767) * 8;
    float4 o[2];
    prep_group((const float4*)(src + off), o);
    ((float4*)out)[2 * g]     = o[0];
    ((float4*)out)[2 * g + 1] = o[1];
}

// ======================== GEMM (tf32 mma.sync, cp.async x3 stages) =========
// C[m, wsel*c_stride + n] = sum_k A[m,k] * W[wsel][n,k]
// A, Wt already tf32-rounded + pk8-permuted along k.
// Block tile 128x128, BK=32. 256 threads = 8 warps (2 M x 4 N), warp 64x32.
// SMEM stage = A(16KB) + B(16KB); 3 stages = 96KB dynamic; 2 CTAs/SM.
#define GSTAGE  32768
#define GSMEM   (3 * GSTAGE + 128)

__global__ void __launch_bounds__(256, 2)
gemm_tf32(const float* __restrict__ A, const float* __restrict__ Wt,
          float* __restrict__ C, size_t c_stride) {
    extern __shared__ char dsmem[];
    const uint32_t sb = (smem_u32(dsmem) + 127u) & ~127u;

    const int tid  = threadIdx.x;
    const int lane = tid & 31;
    const int wid  = tid >> 5;
    const int wm   = wid & 1;
    const int wn   = wid >> 1;
    const int c    = lane & 3;
    const int r8   = lane >> 2;

    const int nb   = blockIdx.x;
    const int wsel = nb >> 2;
    const int n0   = (nb & 3) * 128;
    const int m0   = blockIdx.y * 128;

    const float* Aw = A + (size_t)m0 * 512;
    const float* Bw = Wt + (size_t)wsel * WELEMS + (size_t)n0 * 512;
    float* Cw = C + (size_t)wsel * c_stride;

    float acc[4][4][4];
#pragma unroll
    for (int mt = 0; mt < 4; mt++)
#pragma unroll
        for (int nt = 0; nt < 4; nt++)
#pragma unroll
            for (int i = 0; i < 4; i++) acc[mt][nt][i] = 0.0f;

    auto load_stage = [&](int s, int kt) {
        const uint32_t stage = sb + s * GSTAGE;
#pragma unroll
        for (int i = 0; i < 8; i++) {
            const int cid = tid + i * 256;
            const int isB = cid >> 10;
            const int r   = (cid >> 3) & 127;
            const int ch  = cid & 7;
            const uint32_t so =
                stage + isB * 16384 + r * 128 + (((ch ^ (r & 7)) << 4));
            const float* gp =
                (isB ? Bw : Aw) + (size_t)r * 512 + kt * 32 + ch * 4;
            CPA16(so, gp);
        }
        CPA_COMMIT();
    };

    auto compute = [&](int s) {
        const uint32_t sA = sb + s * GSTAGE + (wm * 64 + r8) * 128 + 8 * (c & 1);
        // B base: +wn*32 rows (wn*4096 bytes)  [R5 fix]
        const uint32_t sB = sb + s * GSTAGE + 16384 + wn * 4096 + r8 * 128 +
                            8 * (c & 1);
#pragma unroll
        for (int g = 0; g < 4; g++) {
            const uint32_t csw = (uint32_t)(((2 * g + (c >> 1)) ^ r8) << 4);
            uint2 lo, hi;
            unsigned a0[4], a1[4], a2[4], a3[4], b0[4], b1[4];
#pragma unroll
            for (int mt = 0; mt < 4; mt++) {
                LDS64(lo, sA + mt * 2048 + csw);
                LDS64(hi, sA + mt * 2048 + 1024 + csw);
                a0[mt] = lo.x; a2[mt] = lo.y; a1[mt] = hi.x; a3[mt] = hi.y;
            }
#pragma unroll
            for (int nt = 0; nt < 4; nt++) {
                LDS64(lo, sB + nt * 1024 + csw);
                b0[nt] = lo.x; b1[nt] = lo.y;
            }
#pragma unroll
            for (int mt = 0; mt < 4; mt++)
#pragma unroll
                for (int nt = 0; nt < 4; nt++)
                    MMA_TF32(acc[mt][nt], a0[mt], a1[mt], a2[mt], a3[mt],
                             b0[nt], b1[nt]);
        }
    };

    load_stage(0, 0);
    load_stage(1, 1);

    int scur = 0, snext = 1, sload = 2;
#pragma unroll 1
    for (int kt = 0; kt < 16; kt++) {
        if (kt < 15) { CPA_WAIT1(); } else { CPA_WAIT0(); }
        __syncthreads();
        if (kt + 2 < 16) load_stage(sload, kt + 2);
        compute(scur);
        const int t = scur; scur = snext; snext = sload; sload = t;
    }

    // Epilogue
#pragma unroll
    for (int mt = 0; mt < 4; mt++) {
        const int row = m0 + wm * 64 + mt * 16 + r8;
#pragma unroll
        for (int nt = 0; nt < 4; nt++) {
            const int col = n0 + wn * 32 + nt * 8 + 2 * c;
            *(float2*)&Cw[(size_t)row * 512 + col] =
                make_float2(acc[mt][nt][0], acc[mt][nt][1]);
            *(float2*)&Cw[(size_t)(row + 8) * 512 + col] =
                make_float2(acc[mt][nt][2], acc[mt][nt][3]);
        }
    }
}

// ======================== attention (tf32 mma.sync) ========================
// One block (128 threads) per (batch, head). Ps overlays dead Qs/Ks storage.
// Epilogue writes tf32-rounded, pk8-permuted fp32 (feeds the Wo GEMM).
__global__ void __launch_bounds__(128, 7)
attn64_tf32(const float* __restrict__ Q, const float* __restrict__ K,
            const float* __restrict__ V, float* __restrict__ At) {
    __shared__ union {
        struct { unsigned Q[64][34]; unsigned K[64][34]; } qk;
        unsigned P[4][16][66];
    } u;
    __shared__ unsigned Vt[32][66];

    const int tid  = threadIdx.x;
    const int lane = tid & 31;
    const int w    = tid >> 5;
    const int c    = lane & 3;
    const int r8   = lane >> 2;

    const int bh = blockIdx.x;
    const int b  = bh >> 4;
    const int h  = bh & 15;
    const size_t rbase = (size_t)b * SEQ * D_MODEL + h * DK;

    const int lrow = tid >> 1;
    const int lc0  = (tid & 1) * 16;
    const int prow = pk8(lrow);
#pragma unroll
    for (int q = 0; q < 4; q++) {
        float4 vq = *(const float4*)(Q + rbase + (size_t)lrow * D_MODEL + lc0 + q * 4);
        float4 vk = *(const float4*)(K + rbase + (size_t)lrow * D_MODEL + lc0 + q * 4);
        float4 vv = *(const float4*)(V + rbase + (size_t)lrow * D_MODEL + lc0 + q * 4);
        const float aq[4] = {vq.x, vq.y, vq.z, vq.w};
        const float ak[4] = {vk.x, vk.y, vk.z, vk.w};
        const float av[4] = {vv.x, vv.y, vv.z, vv.w};
#pragma unroll
        for (int j = 0; j < 4; j++) {
            int col = lc0 + q * 4 + j;
            int pc  = pk8(col);
            u.qk.Q[lrow][pc] = f2tf32(aq[j]);
            u.qk.K[lrow][pc] = f2tf32(ak[j]);
            Vt[col][prow]    = f2tf32(av[j]);
        }
    }
    __syncthreads();

    float s[8][4];
#pragma unroll
    for (int nt = 0; nt < 8; nt++)
#pragma unroll
        for (int i = 0; i < 4; i++) s[nt][i] = 0.0f;

#pragma unroll
    for (int kk = 0; kk < 32; kk += 8) {
        const int kpos = kk + 2 * c;
        uint2 alo = *(const uint2*)&u.qk.Q[w * 16 + r8][kpos];
        uint2 ahi = *(const uint2*)&u.qk.Q[w * 16 + 8 + r8][kpos];
#pragma unroll
        for (int nt = 0; nt < 8; nt++) {
            uint2 bb = *(const uint2*)&u.qk.K[nt * 8 + r8][kpos];
            MMA_TF32(s[nt], alo.x, ahi.x, alo.y, ahi.y, bb.x, bb.y);
        }
    }

    const float scale = 0.17677669529663687f;  // 1/sqrt(32)
#pragma unroll
    for (int nt = 0; nt < 8; nt++)
#pragma unroll
        for (int i = 0; i < 4; i++) s[nt][i] *= scale;

    float m1 = -1e30f, m2 = -1e30f;
#pragma unroll
    for (int nt = 0; nt < 8; nt++) {
        m1 = fmaxf(m1, fmaxf(s[nt][0], s[nt][1]));
        m2 = fmaxf(m2, fmaxf(s[nt][2], s[nt][3]));
    }
    m1 = fmaxf(m1, __shfl_xor_sync(0xffffffffu, m1, 1));
    m1 = fmaxf(m1, __shfl_xor_sync(0xffffffffu, m1, 2));
    m2 = fmaxf(m2, __shfl_xor_sync(0xffffffffu, m2, 1));
    m2 = fmaxf(m2, __shfl_xor_sync(0xffffffffu, m2, 2));

    float sum1 = 0.0f, sum2 = 0.0f;
#pragma unroll
    for (int nt = 0; nt < 8; nt++) {
        s[nt][0] = __expf(s[nt][0] - m1);
        s[nt][1] = __expf(s[nt][1] - m1);
        s[nt][2] = __expf(s[nt][2] - m2);
        s[nt][3] = __expf(s[nt][3] - m2);
        sum1 += s[nt][0] + s[nt][1];
        sum2 += s[nt][2] + s[nt][3];
    }
    sum1 += __shfl_xor_sync(0xffffffffu, sum1, 1);
    sum1 += __shfl_xor_sync(0xffffffffu, sum1, 2);
    sum2 += __shfl_xor_sync(0xffffffffu, sum2, 1);
    sum2 += __shfl_xor_sync(0xffffffffu, sum2, 2);
    const float inv1 = 1.0f / sum1;
    const float inv2 = 1.0f / sum2;

    // All warps must be done reading Qs/Ks before Ps overlays them.
    __syncthreads();

    const int j0 = 2 * c;
    const int p0 = ((j0 & 3) << 1) + (j0 >> 2);
    const int p1 = (((j0 + 1) & 3) << 1) + ((j0 + 1) >> 2);
#pragma unroll
    for (int nt = 0; nt < 8; nt++) {
        u.P[w][r8][nt * 8 + p0]     = f2tf32(s[nt][0] * inv1);
        u.P[w][r8][nt * 8 + p1]     = f2tf32(s[nt][1] * inv1);
        u.P[w][r8 + 8][nt * 8 + p0] = f2tf32(s[nt][2] * inv2);
        u.P[w][r8 + 8][nt * 8 + p1] = f2tf32(s[nt][3] * inv2);
    }
    __syncwarp();

    float o[4][4];
#pragma unroll
    for (int nt = 0; nt < 4; nt++)
#pragma unroll
        for (int i = 0; i < 4; i++) o[nt][i] = 0.0f;

#pragma unroll
    for (int kk = 0; kk < 64; kk += 8) {
        const int kpos = kk + 2 * c;
        uint2 alo = *(const uint2*)&u.P[w][r8][kpos];
        uint2 ahi = *(const uint2*)&u.P[w][r8 + 8][kpos];
#pragma unroll
        for (int nt = 0; nt < 4; nt++) {
            uint2 bb = *(const uint2*)&Vt[nt * 8 + r8][kpos];
            MMA_TF32(o[nt], alo.x, ahi.x, alo.y, ahi.y, bb.x, bb.y);
        }
    }

    // Epilogue: tf32-rounded, pk8-permuted store (GEMM-4 input layout).
    const int row = b * SEQ + w * 16 + r8;
#pragma unroll
    for (int nt = 0; nt < 4; nt++) {
        const int cb = h * DK + nt * 8;
        At[(size_t)row * D_MODEL + cb + p0]       = rtf(o[nt][0]);
        At[(size_t)row * D_MODEL + cb + p1]       = rtf(o[nt][1]);
        At[(size_t)(row + 8) * D_MODEL + cb + p0] = rtf(o[nt][2]);
        At[(size_t)(row + 8) * D_MODEL + cb + p1] = rtf(o[nt][3]);
    }
}

// ======================== launch ===========================================
extern "C" void kernel_launch(void* const* d_in, const int* in_sizes, int n_in,
                              void* d_out, int out_size) {
    (void)in_sizes; (void)n_in; (void)out_size;
    const float* x  = (const float*)d_in[0];
    const float* Wq = (const float*)d_in[1];
    const float* Wk = (const float*)d_in[2];
    const float* Wv = (const float*)d_in[3];
    const float* Wo = (const float*)d_in[4];
    float* out = (float*)d_out;

    void *pxt, *pwt, *pqkv, *pat;
    cudaGetSymbolAddress(&pxt, g_xt);
    cudaGetSymbolAddress(&pwt, g_wt);
    cudaGetSymbolAddress(&pqkv, g_qkv);
    cudaGetSymbolAddress(&pat, g_at);

    cudaFuncSetAttribute(gemm_tf32,
                         cudaFuncAttributeMaxDynamicSharedMemorySize, GSMEM);

    prep_w_kernel<<<512, 256>>>(Wq, Wk, Wv, Wo, (float*)pwt);
    prep_x_kernel<<<32768, 256>>>(x, (float*)pxt);

    // Fused Q,K,V projections: grid.x = 3 weights * 4 n-blocks.
    gemm_tf32<<<dim3(12, M_ROWS / 128), 256, GSMEM>>>(
        (const float*)pxt, (const float*)pwt, (float*)pqkv, MS);

    const float* q = (const float*)pqkv;
    const float* k = q + MS;
    const float* v = k + MS;
    attn64_tf32<<<M_ROWS / SEQ * NUM_HEADS, 128>>>(q, k, v, (float*)pat);

    // Output projection (weight index 3 = Wo).
    gemm_tf32<<<dim3(4, M_ROWS / 128), 256, GSMEM>>>(
        (const float*)pat, (const float*)pwt + 3 * WELEMS, out, 0);
}

// round 6
// speedup vs baseline: 2.6387x; 1.2122x over previous
#include <cuda_runtime.h>
#include <cuda_bf16.h>
#include <cstdint>

// ---------------------------------------------------------------------------
// x:(2048,64,512) fp32, Wq/Wk/Wv/Wo:(512,512) fp32
// out = SDPA(x@WqT, x@WkT, x@WvT) @ WoT    H=16, dk=32, S=64
// M = 131072 rows, D = 512.
//
// mma.sync tf32 path (tcgen05 unavailable: harness compiles compute_103 PTX).
// R6 changes vs R5:
//  * GEMM: warp tile 64x64 (4 warps, 128 thr, 2 CTAs/SM) -> 128B/mma LDS
//  * attention: SMEM pad strides 34->36, 66->68 words => fragment LDS.64
//    bank-pair index gets multiplier 2 (optimal 2-phase) instead of 1
//    (up to 4-way conflicts). Fixes the measured L1=98.4% bound.
// ---------------------------------------------------------------------------

#define D_MODEL   512
#define M_ROWS    131072
#define NUM_HEADS 16
#define SEQ       64
#define DK        32

#define MS        ((size_t)M_ROWS * D_MODEL)
#define WELEMS    ((size_t)D_MODEL * D_MODEL)

// Scratch (device globals are the sanctioned scratch mechanism).
__device__ float g_xt[MS];           // x, tf32-rounded, pk8-permuted cols
__device__ float g_wt[4 * WELEMS];   // Wq,Wk,Wv,Wo, tf32-rounded, permuted
__device__ float g_qkv[3 * MS];      // q, k, v (plain fp32)
__device__ float g_at[MS];           // attn out, tf32-rounded, permuted

// ======================== helpers ==========================================
__device__ __forceinline__ unsigned f2tf32(float f) {
    unsigned r;
    asm("cvt.rna.tf32.f32 %0, %1;" : "=r"(r) : "f"(f));
    return r;
}
__device__ __forceinline__ float rtf(float f) {
    return __uint_as_float(f2tf32(f));
}
__device__ __forceinline__ int pk8(int k) {
    return (k & ~7) + ((k & 3) << 1) + ((k & 7) >> 2);
}
__device__ __forceinline__ uint32_t smem_u32(const void* p) {
    uint32_t a;
    asm("{ .reg .u64 t; cvta.to.shared.u64 t, %1; cvt.u32.u64 %0, t; }"
        : "=r"(a) : "l"(p));
    return a;
}

#define MMA_TF32(d, a0, a1, a2, a3, b0, b1)                                    \
    asm volatile(                                                              \
        "mma.sync.aligned.m16n8k8.row.col.f32.tf32.tf32.f32 "                  \
        "{%0,%1,%2,%3}, {%4,%5,%6,%7}, {%8,%9}, {%0,%1,%2,%3};"                \
        : "+f"(d[0]), "+f"(d[1]), "+f"(d[2]), "+f"(d[3])                       \
        : "r"(a0), "r"(a1), "r"(a2), "r"(a3), "r"(b0), "r"(b1))

#define CPA16(sa, gp)                                                          \
    asm volatile("cp.async.cg.shared.global [%0], [%1], 16;"                   \
                 :: "r"(sa), "l"(gp) : "memory")
#define CPA_COMMIT() asm volatile("cp.async.commit_group;" ::: "memory")
#define CPA_WAIT1()  asm volatile("cp.async.wait_group 1;" ::: "memory")
#define CPA_WAIT0()  asm volatile("cp.async.wait_group 0;" ::: "memory")
#define LDS64(v, a)                                                            \
    asm volatile("ld.shared.v2.u32 {%0,%1}, [%2];"                             \
                 : "=r"((v).x), "=r"((v).y) : "r"(a))

// ======================== prep passes ======================================
__device__ __forceinline__ void prep_group(const float4* in, float4* out) {
    float4 u = in[0], v = in[1];
    out[0] = make_float4(rtf(u.x), rtf(v.x), rtf(u.y), rtf(v.y));
    out[1] = make_float4(rtf(u.z), rtf(v.z), rtf(u.w), rtf(v.w));
}

__global__ void __launch_bounds__(256)
prep_x_kernel(const float* __restrict__ in, float* __restrict__ out) {
    size_t g = (size_t)blockIdx.x * 256 + threadIdx.x;   // group of 8 floats
    float4 o[2];
    prep_group((const float4*)in + 2 * g, o);
    ((float4*)out)[2 * g]     = o[0];
    ((float4*)out)[2 * g + 1] = o[1];
}

__global__ void __launch_bounds__(256)
prep_w_kernel(const float* __restrict__ w0, const float* __restrict__ w1,
              const float* __restrict__ w2, const float* __restrict__ w3,
              float* __restrict__ out) {
    size_t g = (size_t)blockIdx.x * 256 + threadIdx.x;   // group of 8 floats
    int wsel = (int)(g >> 15);                            // 32768 groups per W
    const float* src = wsel == 0 ? w0 : wsel == 1 ? w1 : wsel == 2 ? w2 : w3;
    size_t off = (g & 32767) * 8;
    float4 o[2];
    prep_group((const float4*)(src + off), o);
    ((float4*)out)[2 * g]     = o[0];
    ((float4*)out)[2 * g + 1] = o[1];
}

// ======================== GEMM (tf32 mma.sync, cp.async x3 stages) =========
// Block tile 128x128, BK=32. 128 threads = 4 warps (2M x 2N), warp 64x64.
// SMEM stage = A(16KB) + B(16KB); 3 stages = 96KB dynamic; 2 CTAs/SM.
#define GSTAGE  32768
#define GSMEM   (3 * GSTAGE + 128)

__global__ void __launch_bounds__(128, 2)
gemm_tf32(const float* __restrict__ A, const float* __restrict__ Wt,
          float* __restrict__ C, size_t c_stride) {
    extern __shared__ char dsmem[];
    const uint32_t sb = (smem_u32(dsmem) + 127u) & ~127u;

    const int tid  = threadIdx.x;
    const int lane = tid & 31;
    const int wid  = tid >> 5;
    const int wm   = wid & 1;     // 2 warps along M (64 rows each)
    const int wn   = wid >> 1;    // 2 warps along N (64 cols each)
    const int c    = lane & 3;
    const int r8   = lane >> 2;

    const int nb   = blockIdx.x;
    const int wsel = nb >> 2;
    const int n0   = (nb & 3) * 128;
    const int m0   = blockIdx.y * 128;

    const float* Aw = A + (size_t)m0 * 512;
    const float* Bw = Wt + (size_t)wsel * WELEMS + (size_t)n0 * 512;
    float* Cw = C + (size_t)wsel * c_stride;

    float acc[4][8][4];
#pragma unroll
    for (int mt = 0; mt < 4; mt++)
#pragma unroll
        for (int nt = 0; nt < 8; nt++)
#pragma unroll
            for (int i = 0; i < 4; i++) acc[mt][nt][i] = 0.0f;

    auto load_stage = [&](int s, int kt) {
        const uint32_t stage = sb + s * GSTAGE;
#pragma unroll
        for (int i = 0; i < 16; i++) {
            const int cid = tid + i * 128;           // 0..2047 16B chunks
            const int isB = cid >> 10;
            const int r   = (cid >> 3) & 127;
            const int ch  = cid & 7;
            const uint32_t so =
                stage + isB * 16384 + r * 128 + (((ch ^ (r & 7)) << 4));
            const float* gp =
                (isB ? Bw : Aw) + (size_t)r * 512 + kt * 32 + ch * 4;
            CPA16(so, gp);
        }
        CPA_COMMIT();
    };

    auto compute = [&](int s) {
        const uint32_t sA = sb + s * GSTAGE + (wm * 64 + r8) * 128 + 8 * (c & 1);
        const uint32_t sB = sb + s * GSTAGE + 16384 + wn * 8192 + r8 * 128 +
                            8 * (c & 1);
#pragma unroll
        for (int g = 0; g < 4; g++) {
            const uint32_t csw = (uint32_t)(((2 * g + (c >> 1)) ^ r8) << 4);
            uint2 lo, hi;
            unsigned a0[4], a1[4], a2[4], a3[4], b0[8], b1[8];
#pragma unroll
            for (int mt = 0; mt < 4; mt++) {
                LDS64(lo, sA + mt * 2048 + csw);
                LDS64(hi, sA + mt * 2048 + 1024 + csw);
                a0[mt] = lo.x; a2[mt] = lo.y; a1[mt] = hi.x; a3[mt] = hi.y;
            }
#pragma unroll
            for (int nt = 0; nt < 8; nt++) {
                LDS64(lo, sB + nt * 1024 + csw);
                b0[nt] = lo.x; b1[nt] = lo.y;
            }
#pragma unroll
            for (int mt = 0; mt < 4; mt++)
#pragma unroll
                for (int nt = 0; nt < 8; nt++)
                    MMA_TF32(acc[mt][nt], a0[mt], a1[mt], a2[mt], a3[mt],
                             b0[nt], b1[nt]);
        }
    };

    load_stage(0, 0);
    load_stage(1, 1);

    int scur = 0, snext = 1, sload = 2;
#pragma unroll 1
    for (int kt = 0; kt < 16; kt++) {
        if (kt < 15) { CPA_WAIT1(); } else { CPA_WAIT0(); }
        __syncthreads();
        if (kt + 2 < 16) load_stage(sload, kt + 2);
        compute(scur);
        const int t = scur; scur = snext; snext = sload; sload = t;
    }

    // Epilogue
#pragma unroll
    for (int mt = 0; mt < 4; mt++) {
        const int row = m0 + wm * 64 + mt * 16 + r8;
#pragma unroll
        for (int nt = 0; nt < 8; nt++) {
            const int col = n0 + wn * 64 + nt * 8 + 2 * c;
            *(float2*)&Cw[(size_t)row * 512 + col] =
                make_float2(acc[mt][nt][0], acc[mt][nt][1]);
            *(float2*)&Cw[(size_t)(row + 8) * 512 + col] =
                make_float2(acc[mt][nt][2], acc[mt][nt][3]);
        }
    }
}

// ======================== attention (tf32 mma.sync) ========================
// One block (128 threads) per (batch, head). Ps overlays dead Qs/Ks storage.
// Row pads 36 / 68 words -> LDS.64 bank-pair multiplier 2 (optimal 2-phase).
__global__ void __launch_bounds__(128, 7)
attn64_tf32(const float* __restrict__ Q, const float* __restrict__ K,
            const float* __restrict__ V, float* __restrict__ At) {
    __shared__ union {
        struct { unsigned Q[64][36]; unsigned K[64][36]; } qk;
        unsigned P[4][16][68];
    } u;
    __shared__ unsigned Vt[32][68];

    const int tid  = threadIdx.x;
    const int lane = tid & 31;
    const int w    = tid >> 5;
    const int c    = lane & 3;
    const int r8   = lane >> 2;

    const int bh = blockIdx.x;
    const int b  = bh >> 4;
    const int h  = bh & 15;
    const size_t rbase = (size_t)b * SEQ * D_MODEL + h * DK;

    const int lrow = tid >> 1;
    const int lc0  = (tid & 1) * 16;
    const int prow = pk8(lrow);
#pragma unroll
    for (int q = 0; q < 4; q++) {
        float4 vq = *(const float4*)(Q + rbase + (size_t)lrow * D_MODEL + lc0 + q * 4);
        float4 vk = *(const float4*)(K + rbase + (size_t)lrow * D_MODEL + lc0 + q * 4);
        float4 vv = *(const float4*)(V + rbase + (size_t)lrow * D_MODEL + lc0 + q * 4);
        const float aq[4] = {vq.x, vq.y, vq.z, vq.w};
        const float ak[4] = {vk.x, vk.y, vk.z, vk.w};
        const float av[4] = {vv.x, vv.y, vv.z, vv.w};
#pragma unroll
        for (int j = 0; j < 4; j++) {
            int col = lc0 + q * 4 + j;
            int pc  = pk8(col);
            u.qk.Q[lrow][pc] = f2tf32(aq[j]);
            u.qk.K[lrow][pc] = f2tf32(ak[j]);
            Vt[col][prow]    = f2tf32(av[j]);
        }
    }
    __syncthreads();

    float s[8][4];
#pragma unroll
    for (int nt = 0; nt < 8; nt++)
#pragma unroll
        for (int i = 0; i < 4; i++) s[nt][i] = 0.0f;

#pragma unroll
    for (int kk = 0; kk < 32; kk += 8) {
        const int kpos = kk + 2 * c;
        uint2 alo = *(const uint2*)&u.qk.Q[w * 16 + r8][kpos];
        uint2 ahi = *(const uint2*)&u.qk.Q[w * 16 + 8 + r8][kpos];
#pragma unroll
        for (int nt = 0; nt < 8; nt++) {
            uint2 bb = *(const uint2*)&u.qk.K[nt * 8 + r8][kpos];
            MMA_TF32(s[nt], alo.x, ahi.x, alo.y, ahi.y, bb.x, bb.y);
        }
    }

    const float scale = 0.17677669529663687f;  // 1/sqrt(32)
#pragma unroll
    for (int nt = 0; nt < 8; nt++)
#pragma unroll
        for (int i = 0; i < 4; i++) s[nt][i] *= scale;

    float m1 = -1e30f, m2 = -1e30f;
#pragma unroll
    for (int nt = 0; nt < 8; nt++) {
        m1 = fmaxf(m1, fmaxf(s[nt][0], s[nt][1]));
        m2 = fmaxf(m2, fmaxf(s[nt][2], s[nt][3]));
    }
    m1 = fmaxf(m1, __shfl_xor_sync(0xffffffffu, m1, 1));
    m1 = fmaxf(m1, __shfl_xor_sync(0xffffffffu, m1, 2));
    m2 = fmaxf(m2, __shfl_xor_sync(0xffffffffu, m2, 1));
    m2 = fmaxf(m2, __shfl_xor_sync(0xffffffffu, m2, 2));

    float sum1 = 0.0f, sum2 = 0.0f;
#pragma unroll
    for (int nt = 0; nt < 8; nt++) {
        s[nt][0] = __expf(s[nt][0] - m1);
        s[nt][1] = __expf(s[nt][1] - m1);
        s[nt][2] = __expf(s[nt][2] - m2);
        s[nt][3] = __expf(s[nt][3] - m2);
        sum1 += s[nt][0] + s[nt][1];
        sum2 += s[nt][2] + s[nt][3];
    }
    sum1 += __shfl_xor_sync(0xffffffffu, sum1, 1);
    sum1 += __shfl_xor_sync(0xffffffffu, sum1, 2);
    sum2 += __shfl_xor_sync(0xffffffffu, sum2, 1);
    sum2 += __shfl_xor_sync(0xffffffffu, sum2, 2);
    const float inv1 = 1.0f / sum1;
    const float inv2 = 1.0f / sum2;

    // All warps must be done reading Qs/Ks before Ps overlays them.
    __syncthreads();

    const int j0 = 2 * c;
    const int p0 = ((j0 & 3) << 1) + (j0 >> 2);
    const int p1 = (((j0 + 1) & 3) << 1) + ((j0 + 1) >> 2);
#pragma unroll
    for (int nt = 0; nt < 8; nt++) {
        u.P[w][r8][nt * 8 + p0]     = f2tf32(s[nt][0] * inv1);
        u.P[w][r8][nt * 8 + p1]     = f2tf32(s[nt][1] * inv1);
        u.P[w][r8 + 8][nt * 8 + p0] = f2tf32(s[nt][2] * inv2);
        u.P[w][r8 + 8][nt * 8 + p1] = f2tf32(s[nt][3] * inv2);
    }
    __syncwarp();

    float o[4][4];
#pragma unroll
    for (int nt = 0; nt < 4; nt++)
#pragma unroll
        for (int i = 0; i < 4; i++) o[nt][i] = 0.0f;

#pragma unroll
    for (int kk = 0; kk < 64; kk += 8) {
        const int kpos = kk + 2 * c;
        uint2 alo = *(const uint2*)&u.P[w][r8][kpos];
        uint2 ahi = *(const uint2*)&u.P[w][r8 + 8][kpos];
#pragma unroll
        for (int nt = 0; nt < 4; nt++) {
            uint2 bb = *(const uint2*)&Vt[nt * 8 + r8][kpos];
            MMA_TF32(o[nt], alo.x, ahi.x, alo.y, ahi.y, bb.x, bb.y);
        }
    }

    // Epilogue: tf32-rounded, pk8-permuted store (GEMM-4 input layout).
    const int row = b * SEQ + w * 16 + r8;
#pragma unroll
    for (int nt = 0; nt < 4; nt++) {
        const int cb = h * DK + nt * 8;
        At[(size_t)row * D_MODEL + cb + p0]       = rtf(o[nt][0]);
        At[(size_t)row * D_MODEL + cb + p1]       = rtf(o[nt][1]);
        At[(size_t)(row + 8) * D_MODEL + cb + p0] = rtf(o[nt][2]);
        At[(size_t)(row + 8) * D_MODEL + cb + p1] = rtf(o[nt][3]);
    }
}

// ======================== launch ===========================================
extern "C" void kernel_launch(void* const* d_in, const int* in_sizes, int n_in,
                              void* d_out, int out_size) {
    (void)in_sizes; (void)n_in; (void)out_size;
    const float* x  = (const float*)d_in[0];
    const float* Wq = (const float*)d_in[1];
    const float* Wk = (const float*)d_in[2];
    const float* Wv = (const float*)d_in[3];
    const float* Wo = (const float*)d_in[4];
    float* out = (float*)d_out;

    void *pxt, *pwt, *pqkv, *pat;
    cudaGetSymbolAddress(&pxt, g_xt);
    cudaGetSymbolAddress(&pwt, g_wt);
    cudaGetSymbolAddress(&pqkv, g_qkv);
    cudaGetSymbolAddress(&pat, g_at);

    cudaFuncSetAttribute(gemm_tf32,
                         cudaFuncAttributeMaxDynamicSharedMemorySize, GSMEM);

    prep_w_kernel<<<512, 256>>>(Wq, Wk, Wv, Wo, (float*)pwt);
    prep_x_kernel<<<32768, 256>>>(x, (float*)pxt);

    // Fused Q,K,V projections: grid.x = 3 weights * 4 n-blocks.
    gemm_tf32<<<dim3(12, M_ROWS / 128), 128, GSMEM>>>(
        (const float*)pxt, (const float*)pwt, (float*)pqkv, MS);

    const float* q = (const float*)pqkv;
    const float* k = q + MS;
    const float* v = k + MS;
    attn64_tf32<<<M_ROWS / SEQ * NUM_HEADS, 128>>>(q, k, v, (float*)pat);

    // Output projection (weight index 3 = Wo).
    gemm_tf32<<<dim3(4, M_ROWS / 128), 128, GSMEM>>>(
        (const float*)pat, (const float*)pwt + 3 * WELEMS, out, 0);
}